// round 1
// baseline (speedup 1.0000x reference)
#include <cuda_runtime.h>

// ---------------------------------------------------------------------------
// Symmetric contraction (MACE-style) for GB300.
//   out[b, o_p*U + u] += c_p * x0[i0[b], w_p*U + u] * prod_k x1[b, idx_{p,k}*U + u]
//
// Strategy:
//   Setup kernels (cheap, run every launch, graph-capturable):
//     S0: sort paths by (output segment, degree); pack idx into one int/path.
//     S1: histogram of i0 (<=16 bins) + prefix sum.
//     S2: scatter batch indices into i0-sorted order.
//     S3: build per-block work descriptors (each block = one i0 bin chunk).
//     S4: build coefficient-folded gathered table g0c[row][sorted_path][u].
//   Main kernel:
//     1 block = 128 threads (thread = u), one i0 bin, TBB=16 batch rows,
//     processed 4-at-a-time. g0c staged in smem once per block. x1 rows
//     staged lane-interleaved [s][u][4] so one LDS.128 feeds 4 batch rows.
//     Paths pre-sorted by segment -> accumulators live in registers.
// ---------------------------------------------------------------------------

#define U       128
#define NSEG    16
#define S_SEG   32
#define NX0     10
#define TBB     16      // batch rows per block
#define NL      4       // concurrent batch rows (lanes)
#define PCAP    256     // max total paths (actual 192)
#define BSORT_CAP 32768
#define BINFO_CAP 8192

struct BInfo { int bin; int start; int count; };

__device__ int   d_binstart[24];
__device__ int   d_cursor[20];
__device__ int   d_bsort[BSORT_CAP];
__device__ BInfo d_binfo[BINFO_CAP];
__device__ int   d_meta[PCAP];
__device__ int   d_ends[NSEG * 3];
__device__ int   d_spw[PCAP];
__device__ float d_spc[PCAP];
__device__ float d_g0c[NX0 * PCAP * U];   // [row][sorted_path][u]

// ---------------- S0: sort paths by (segment, degree), pack indices --------
__global__ void k_sortpaths(const int* idx1, const int* w1, const int* o1, const float* c1,
                            const int* idx2, const int* w2, const int* o2, const float* c2,
                            const int* idx3, const int* w3, const int* o3, const float* c3,
                            int P1, int P2, int P3) {
    if (threadIdx.x != 0 || blockIdx.x != 0) return;
    int sp = 0;
    for (int seg = 0; seg < NSEG; ++seg) {
        for (int p = 0; p < P1 && sp < PCAP; ++p) if (o1[p] == seg) {
            d_meta[sp] = idx1[p];
            d_spw[sp] = w1[p]; d_spc[sp] = c1[p]; ++sp;
        }
        d_ends[seg * 3 + 0] = sp;
        for (int p = 0; p < P2 && sp < PCAP; ++p) if (o2[p] == seg) {
            d_meta[sp] = idx2[p * 2] | (idx2[p * 2 + 1] << 8);
            d_spw[sp] = w2[p]; d_spc[sp] = c2[p]; ++sp;
        }
        d_ends[seg * 3 + 1] = sp;
        for (int p = 0; p < P3 && sp < PCAP; ++p) if (o3[p] == seg) {
            d_meta[sp] = idx3[p * 3] | (idx3[p * 3 + 1] << 8) | (idx3[p * 3 + 2] << 16);
            d_spw[sp] = w3[p]; d_spc[sp] = c3[p]; ++sp;
        }
        d_ends[seg * 3 + 2] = sp;
    }
}

// ---------------- S1: histogram + prefix sum of i0 -------------------------
__global__ void k_hist(const int* i0, int B) {
    __shared__ int h[20];
    int t = threadIdx.x;
    if (t < 20) h[t] = 0;
    __syncthreads();
    for (int b = t; b < B; b += blockDim.x) atomicAdd(&h[i0[b] & 15], 1);
    __syncthreads();
    if (t == 0) {
        int run = 0;
        for (int bin = 0; bin < 16; ++bin) {
            d_binstart[bin] = run; d_cursor[bin] = run; run += h[bin];
        }
        d_binstart[16] = run;
    }
}

// ---------------- S2: scatter batch indices into bin-sorted order ----------
__global__ void k_scatter(const int* i0, int B) {
    int b = blockIdx.x * blockDim.x + threadIdx.x;
    if (b < B) {
        int pos = atomicAdd(&d_cursor[i0[b] & 15], 1);
        if (pos < BSORT_CAP) d_bsort[pos] = b;
    }
}

// ---------------- S3: build per-block work descriptors ---------------------
__global__ void k_binfo(int gridMain) {
    if (threadIdx.x != 0 || blockIdx.x != 0) return;
    int nb = 0;
    for (int bin = 0; bin < 16; ++bin) {
        int s = d_binstart[bin], e = d_binstart[bin + 1];
        for (int off = s; off < e && nb < BINFO_CAP; off += TBB) {
            d_binfo[nb].bin = bin;
            d_binfo[nb].start = off;
            d_binfo[nb].count = min(TBB, e - off);
            ++nb;
        }
    }
    for (; nb < gridMain && nb < BINFO_CAP; ++nb) d_binfo[nb].count = 0;
}

// ---------------- S4: coefficient-folded gathered table --------------------
__global__ void k_g0c(const float* __restrict__ x0, int Ptot, int rowlen) {
    int i = blockIdx.x * blockDim.x + threadIdx.x;
    int tot = NX0 * Ptot * U;
    if (i >= tot) return;
    int u  = i & (U - 1);
    int sp = (i >> 7) % Ptot;
    int r  = i / (Ptot * U);
    d_g0c[r * (PCAP * U) + sp * U + u] =
        x0[(size_t)r * rowlen + d_spw[sp] * U + u] * d_spc[sp];
}

// ---------------- Main contraction kernel ----------------------------------
__global__ __launch_bounds__(128, 1)
void k_main(const float* __restrict__ x1, float* __restrict__ out, int B, int Ptot) {
    extern __shared__ float sm[];
    float* g0s = sm;                          // [Ptot][U]
    float* x1s = sm + Ptot * U;               // [S][U][NL] lane-interleaved
    int* metas = (int*)(x1s + S_SEG * U * NL);// [Ptot]
    int* endss = metas + Ptot;                // [NSEG*3]

    BInfo bi = d_binfo[blockIdx.x];
    if (bi.count <= 0) return;
    const int u = threadIdx.x;

    // stage g0c table + path metadata once per block
    {
        const float4* src = (const float4*)(d_g0c + (size_t)bi.bin * (PCAP * U));
        float4* dst = (float4*)g0s;
        int n4 = (Ptot * U) >> 2;
        for (int i = u; i < n4; i += 128) dst[i] = src[i];
        for (int i = u; i < Ptot; i += 128) metas[i] = d_meta[i];
        if (u < NSEG * 3) endss[u] = d_ends[u];
    }
    __syncthreads();

    for (int r = 0; r < bi.count; r += NL) {
        if (r) __syncthreads();   // protect x1s reuse
        int nb = bi.count - r; if (nb > NL) nb = NL;
        int b0 = d_bsort[bi.start + r];
        int b1 = d_bsort[min(bi.start + r + 1, B - 1)];
        int b2 = d_bsort[min(bi.start + r + 2, B - 1)];
        int b3 = d_bsort[min(bi.start + r + 3, B - 1)];
        const float* r0 = x1 + (size_t)b0 * (S_SEG * U);
        const float* r1 = x1 + (size_t)b1 * (S_SEG * U);
        const float* r2 = x1 + (size_t)b2 * (S_SEG * U);
        const float* r3 = x1 + (size_t)b3 * (S_SEG * U);

        // stage x1 rows lane-interleaved: x1s[(s*U+u)*4 + lane]
        #pragma unroll
        for (int s = 0; s < S_SEG; ++s) {
            float4 v;
            v.x = __ldg(r0 + s * U + u);
            v.y = __ldg(r1 + s * U + u);
            v.z = __ldg(r2 + s * U + u);
            v.w = __ldg(r3 + s * U + u);
            ((float4*)x1s)[s * U + u] = v;
        }
        __syncthreads();

        const float4* xb = (const float4*)x1s;
        int p = 0;
        #pragma unroll 1
        for (int seg = 0; seg < NSEG; ++seg) {
            float a0 = 0.f, a1 = 0.f, a2 = 0.f, a3 = 0.f;
            int e1 = endss[seg * 3 + 0];
            int e2 = endss[seg * 3 + 1];
            int e3 = endss[seg * 3 + 2];
            // degree-1 paths
            for (; p < e1; ++p) {
                float g = g0s[p * U + u];
                int m = metas[p];
                float4 xa = xb[(m & 255) * U + u];
                a0 = fmaf(g, xa.x, a0);
                a1 = fmaf(g, xa.y, a1);
                a2 = fmaf(g, xa.z, a2);
                a3 = fmaf(g, xa.w, a3);
            }
            // degree-2 paths
            for (; p < e2; ++p) {
                float g = g0s[p * U + u];
                int m = metas[p];
                float4 xa = xb[(m & 255) * U + u];
                float4 xc = xb[((m >> 8) & 255) * U + u];
                a0 = fmaf(g, xa.x * xc.x, a0);
                a1 = fmaf(g, xa.y * xc.y, a1);
                a2 = fmaf(g, xa.z * xc.z, a2);
                a3 = fmaf(g, xa.w * xc.w, a3);
            }
            // degree-3 paths
            for (; p < e3; ++p) {
                float g = g0s[p * U + u];
                int m = metas[p];
                float4 xa = xb[(m & 255) * U + u];
                float4 xc = xb[((m >> 8) & 255) * U + u];
                float4 xd = xb[((m >> 16) & 255) * U + u];
                a0 = fmaf(g, xa.x * xc.x * xd.x, a0);
                a1 = fmaf(g, xa.y * xc.y * xd.y, a1);
                a2 = fmaf(g, xa.z * xc.z * xd.z, a2);
                a3 = fmaf(g, xa.w * xc.w * xd.w, a3);
            }
            size_t so = (size_t)seg * U + u;
            out[(size_t)b0 * (NSEG * U) + so] = a0;
            if (nb > 1) out[(size_t)b1 * (NSEG * U) + so] = a1;
            if (nb > 2) out[(size_t)b2 * (NSEG * U) + so] = a2;
            if (nb > 3) out[(size_t)b3 * (NSEG * U) + so] = a3;
        }
    }
}

// ---------------- launch ----------------------------------------------------
extern "C" void kernel_launch(void* const* d_in, const int* in_sizes, int n_in,
                              void* d_out, int out_size) {
    const float* x0   = (const float*)d_in[0];
    const int*   i0   = (const int*)  d_in[1];
    const float* x1   = (const float*)d_in[2];
    const int*   idx1 = (const int*)  d_in[3];
    const int*   w1   = (const int*)  d_in[4];
    const int*   o1   = (const int*)  d_in[5];
    const float* c1   = (const float*)d_in[6];
    const int*   idx2 = (const int*)  d_in[7];
    const int*   w2   = (const int*)  d_in[8];
    const int*   o2   = (const int*)  d_in[9];
    const float* c2   = (const float*)d_in[10];
    const int*   idx3 = (const int*)  d_in[11];
    const int*   w3   = (const int*)  d_in[12];
    const int*   o3   = (const int*)  d_in[13];
    const float* c3   = (const float*)d_in[14];

    int P1 = in_sizes[4], P2 = in_sizes[8], P3 = in_sizes[12];
    int Ptot = P1 + P2 + P3;
    int B = in_sizes[1];
    int rowlen = in_sizes[0] / NX0;   // C*U

    k_sortpaths<<<1, 1>>>(idx1, w1, o1, c1, idx2, w2, o2, c2,
                          idx3, w3, o3, c3, P1, P2, P3);
    k_hist<<<1, 256>>>(i0, B);
    k_scatter<<<(B + 255) / 256, 256>>>(i0, B);
    int gridMain = (B + TBB - 1) / TBB + 16;
    k_binfo<<<1, 1>>>(gridMain);
    int tot = NX0 * Ptot * U;
    k_g0c<<<(tot + 255) / 256, 256>>>(x0, Ptot, rowlen);

    size_t smem = (size_t)Ptot * U * 4 + (size_t)S_SEG * U * NL * 4
                + (size_t)Ptot * 4 + NSEG * 3 * 4;
    cudaFuncSetAttribute(k_main, cudaFuncAttributeMaxDynamicSharedMemorySize,
                         (int)smem);
    k_main<<<gridMain, 128, smem>>>(x1, (float*)d_out, B, Ptot);
}

// round 2
// speedup vs baseline: 2.1616x; 2.1616x over previous
#include <cuda_runtime.h>

// ---------------------------------------------------------------------------
// Symmetric contraction (MACE-style) for GB300 — R2.
//   out[b, o_p*U + u] += c_p * x0[i0[b], w_p*U + u] * prod_k x1[b, idx_{p,k}*U + u]
//
// R2 changes vs R1:
//   * setup kernels fully parallelized (R1 had two single-thread kernels
//     costing ~200us total)
//   * k_main: 512 threads (16 warps) per block; 4 teams of 128 threads share
//     the staged g0 table and x1 rows, splitting output segments (cost-
//     balanced) -> LDS latency hidden, smem crossbar saturated
//   * TBB 16 -> 32: fewer blocks, g0 staging amortized, smaller wave tail
// ---------------------------------------------------------------------------

#define U       128
#define NSEG    16
#define S_SEG   32
#define NX0     10
#define TBB     32      // batch rows per block
#define NL      4       // concurrent batch rows
#define NTEAM   4       // segment-split teams (512 threads total)
#define PCAP    256
#define BSORT_CAP 32768
#define BINFO_CAP 8192

struct BInfo { int bin; int start; int count; };

__device__ int   d_binstart[24];
__device__ int   d_cursor[20];
__device__ int   d_bsort[BSORT_CAP];
__device__ BInfo d_binfo[BINFO_CAP];
__device__ int   d_meta[PCAP];
__device__ int   d_ends[NSEG * 3];
__device__ int   d_tseg[NTEAM + 1];
__device__ int   d_spw[PCAP];
__device__ float d_spc[PCAP];
__device__ float d_g0c[NX0 * PCAP * U];   // [row][sorted_path][u]

// ---------------- S0: parallel counting sort of paths by (seg, degree) -----
__global__ void k_sortpaths(const int* idx1, const int* w1, const int* o1, const float* c1,
                            const int* idx2, const int* w2, const int* o2, const float* c2,
                            const int* idx3, const int* w3, const int* o3, const float* c3,
                            int P1, int P2, int P3) {
    __shared__ int cnt[NSEG * 3];
    __shared__ int cur[NSEG * 3];
    int t = threadIdx.x;
    int Ptot = P1 + P2 + P3;
    if (t < NSEG * 3) cnt[t] = 0;
    __syncthreads();

    for (int p = t; p < Ptot; p += blockDim.x) {
        int key;
        if (p < P1)            key = o1[p] * 3 + 0;
        else if (p < P1 + P2)  key = o2[p - P1] * 3 + 1;
        else                   key = o3[p - P1 - P2] * 3 + 2;
        atomicAdd(&cnt[key], 1);
    }
    __syncthreads();

    if (t == 0) {
        // exclusive scan -> cur; class ends -> d_ends
        int run = 0;
        for (int k = 0; k < NSEG * 3; ++k) {
            cur[k] = run;
            run += cnt[k];
            d_ends[k] = run;
        }
        // cost-balanced contiguous segment partition into NTEAM teams.
        // per-path crossbar cost ~ 1 (g0) + 4*deg  -> weights 5/9/13
        float segc[NSEG];
        float tot = 0.f;
        for (int s = 0; s < NSEG; ++s) {
            segc[s] = 5.f * cnt[s * 3] + 9.f * cnt[s * 3 + 1] + 13.f * cnt[s * 3 + 2];
            tot += segc[s];
        }
        d_tseg[0] = 0; d_tseg[NTEAM] = NSEG;
        float acc = 0.f; int team = 1;
        for (int s = 0; s < NSEG && team < NTEAM; ++s) {
            acc += segc[s];
            if (acc >= tot * team / NTEAM) { d_tseg[team] = s + 1; ++team; }
        }
        for (; team < NTEAM; ++team) d_tseg[team] = NSEG;
    }
    __syncthreads();

    for (int p = t; p < Ptot; p += blockDim.x) {
        int key, meta, w; float c;
        if (p < P1) {
            key = o1[p] * 3 + 0; meta = idx1[p]; w = w1[p]; c = c1[p];
        } else if (p < P1 + P2) {
            int q = p - P1;
            key = o2[q] * 3 + 1;
            meta = idx2[q * 2] | (idx2[q * 2 + 1] << 8);
            w = w2[q]; c = c2[q];
        } else {
            int q = p - P1 - P2;
            key = o3[q] * 3 + 2;
            meta = idx3[q * 3] | (idx3[q * 3 + 1] << 8) | (idx3[q * 3 + 2] << 16);
            w = w3[q]; c = c3[q];
        }
        int pos = atomicAdd(&cur[key], 1);
        d_meta[pos] = meta; d_spw[pos] = w; d_spc[pos] = c;
    }
}

// ---------------- S1: histogram + prefix sum of i0 -------------------------
__global__ void k_hist(const int* __restrict__ i0, int B) {
    __shared__ int h[20];
    int t = threadIdx.x;
    if (t < 20) h[t] = 0;
    __syncthreads();
    for (int b = blockIdx.x * blockDim.x + t; b < B; b += blockDim.x * gridDim.x)
        atomicAdd(&h[i0[b] & 15], 1);
    __syncthreads();
    if (t < 16 && h[t]) atomicAdd(&d_cursor[16 + 0] + t - 16 + 0, 0); // no-op keep simple
    if (blockIdx.x == 0 && t == 0) {}  // placeholder
    // single-block launch in practice:
    if (t == 0 && gridDim.x == 1) {
        int run = 0;
        for (int bin = 0; bin < 16; ++bin) {
            d_binstart[bin] = run; d_cursor[bin] = run; run += h[bin];
        }
        d_binstart[16] = run;
    }
}

// ---------------- S2: scatter batch indices into bin-sorted order ----------
__global__ void k_scatter(const int* __restrict__ i0, int B) {
    int b = blockIdx.x * blockDim.x + threadIdx.x;
    if (b < B) {
        int pos = atomicAdd(&d_cursor[i0[b] & 15], 1);
        if (pos < BSORT_CAP) d_bsort[pos] = b;
    }
}

// ---------------- S3: parallel per-block work descriptors ------------------
__global__ void k_binfo(int gridMain) {
    __shared__ int pref[17];
    int t = threadIdx.x;
    if (t == 0) {
        int run = 0;
        for (int bin = 0; bin < 16; ++bin) {
            pref[bin] = run;
            int c = d_binstart[bin + 1] - d_binstart[bin];
            run += (c + TBB - 1) / TBB;
        }
        pref[16] = run;
    }
    __syncthreads();
    int nb = pref[16];
    for (int i = t; i < gridMain && i < BINFO_CAP; i += blockDim.x) {
        if (i >= nb) { d_binfo[i].count = 0; continue; }
        int bin = 0;
        while (pref[bin + 1] <= i) ++bin;
        int start = d_binstart[bin] + (i - pref[bin]) * TBB;
        d_binfo[i].bin = bin;
        d_binfo[i].start = start;
        d_binfo[i].count = min(TBB, d_binstart[bin + 1] - start);
    }
}

// ---------------- S4: coefficient-folded gathered table --------------------
__global__ void k_g0c(const float* __restrict__ x0, int Ptot, int rowlen) {
    int i = blockIdx.x * blockDim.x + threadIdx.x;
    int tot = NX0 * Ptot * U;
    if (i >= tot) return;
    int u  = i & (U - 1);
    int sp = (i >> 7) % Ptot;
    int r  = i / (Ptot * U);
    d_g0c[r * (PCAP * U) + sp * U + u] =
        x0[(size_t)r * rowlen + d_spw[sp] * U + u] * d_spc[sp];
}

// ---------------- Main contraction kernel ----------------------------------
__global__ __launch_bounds__(512, 1)
void k_main(const float* __restrict__ x1, float* __restrict__ out, int B, int Ptot) {
    extern __shared__ float sm[];
    float* g0s = sm;                            // [Ptot][U]
    float* x1s = sm + Ptot * U;                 // [S][U][NL] lane-interleaved
    int* metas = (int*)(x1s + S_SEG * U * NL);  // [Ptot]
    int* endss = metas + Ptot;                  // [NSEG*3]
    int* tsegs = endss + NSEG * 3;              // [NTEAM+1]

    BInfo bi = d_binfo[blockIdx.x];
    if (bi.count <= 0) return;
    const int tid  = threadIdx.x;
    const int u    = tid & (U - 1);
    const int team = tid >> 7;

    // stage g0c table + path metadata once per block (all 512 threads)
    {
        const float4* src = (const float4*)(d_g0c + (size_t)bi.bin * (PCAP * U));
        float4* dst = (float4*)g0s;
        int n4 = (Ptot * U) >> 2;
        for (int i = tid; i < n4; i += 512) dst[i] = __ldg(src + i);
        for (int i = tid; i < Ptot; i += 512) metas[i] = d_meta[i];
        if (tid < NSEG * 3) endss[tid] = d_ends[tid];
        if (tid < NTEAM + 1) tsegs[tid] = d_tseg[tid];
    }
    __syncthreads();

    const int segLo = tsegs[team];
    const int segHi = tsegs[team + 1];

    for (int r = 0; r < bi.count; r += NL) {
        if (r) __syncthreads();   // protect x1s reuse
        int nb = bi.count - r; if (nb > NL) nb = NL;
        int b0 = d_bsort[bi.start + r];
        int b1 = d_bsort[min(bi.start + r + 1, B - 1)];
        int b2 = d_bsort[min(bi.start + r + 2, B - 1)];
        int b3 = d_bsort[min(bi.start + r + 3, B - 1)];
        const float* r0 = x1 + (size_t)b0 * (S_SEG * U);
        const float* r1 = x1 + (size_t)b1 * (S_SEG * U);
        const float* r2 = x1 + (size_t)b2 * (S_SEG * U);
        const float* r3 = x1 + (size_t)b3 * (S_SEG * U);

        // stage x1 rows lane-interleaved with all 512 threads:
        // x1s[(s*U+uu)*4 + lane]
        for (int i = tid; i < S_SEG * U; i += 512) {
            float4 v;
            v.x = __ldg(r0 + i);
            v.y = __ldg(r1 + i);
            v.z = __ldg(r2 + i);
            v.w = __ldg(r3 + i);
            ((float4*)x1s)[i] = v;
        }
        __syncthreads();

        const float4* xb = (const float4*)x1s;
        #pragma unroll 1
        for (int seg = segLo; seg < segHi; ++seg) {
            float a0 = 0.f, a1 = 0.f, a2 = 0.f, a3 = 0.f;
            int p  = seg ? endss[seg * 3 - 1] : 0;
            int e1 = endss[seg * 3 + 0];
            int e2 = endss[seg * 3 + 1];
            int e3 = endss[seg * 3 + 2];
            // degree-1 paths
            for (; p < e1; ++p) {
                float g = g0s[p * U + u];
                int m = metas[p];
                float4 xa = xb[(m & 255) * U + u];
                a0 = fmaf(g, xa.x, a0);
                a1 = fmaf(g, xa.y, a1);
                a2 = fmaf(g, xa.z, a2);
                a3 = fmaf(g, xa.w, a3);
            }
            // degree-2 paths
            for (; p < e2; ++p) {
                float g = g0s[p * U + u];
                int m = metas[p];
                float4 xa = xb[(m & 255) * U + u];
                float4 xc = xb[((m >> 8) & 255) * U + u];
                a0 = fmaf(g, xa.x * xc.x, a0);
                a1 = fmaf(g, xa.y * xc.y, a1);
                a2 = fmaf(g, xa.z * xc.z, a2);
                a3 = fmaf(g, xa.w * xc.w, a3);
            }
            // degree-3 paths
            for (; p < e3; ++p) {
                float g = g0s[p * U + u];
                int m = metas[p];
                float4 xa = xb[(m & 255) * U + u];
                float4 xc = xb[((m >> 8) & 255) * U + u];
                float4 xd = xb[((m >> 16) & 255) * U + u];
                a0 = fmaf(g, xa.x * xc.x * xd.x, a0);
                a1 = fmaf(g, xa.y * xc.y * xd.y, a1);
                a2 = fmaf(g, xa.z * xc.z * xd.z, a2);
                a3 = fmaf(g, xa.w * xc.w * xd.w, a3);
            }
            size_t so = (size_t)seg * U + u;
            out[(size_t)b0 * (NSEG * U) + so] = a0;
            if (nb > 1) out[(size_t)b1 * (NSEG * U) + so] = a1;
            if (nb > 2) out[(size_t)b2 * (NSEG * U) + so] = a2;
            if (nb > 3) out[(size_t)b3 * (NSEG * U) + so] = a3;
        }
    }
}

// ---------------- launch ----------------------------------------------------
extern "C" void kernel_launch(void* const* d_in, const int* in_sizes, int n_in,
                              void* d_out, int out_size) {
    const float* x0   = (const float*)d_in[0];
    const int*   i0   = (const int*)  d_in[1];
    const float* x1   = (const float*)d_in[2];
    const int*   idx1 = (const int*)  d_in[3];
    const int*   w1   = (const int*)  d_in[4];
    const int*   o1   = (const int*)  d_in[5];
    const float* c1   = (const float*)d_in[6];
    const int*   idx2 = (const int*)  d_in[7];
    const int*   w2   = (const int*)  d_in[8];
    const int*   o2   = (const int*)  d_in[9];
    const float* c2   = (const float*)d_in[10];
    const int*   idx3 = (const int*)  d_in[11];
    const int*   w3   = (const int*)  d_in[12];
    const int*   o3   = (const int*)  d_in[13];
    const float* c3   = (const float*)d_in[14];

    int P1 = in_sizes[4], P2 = in_sizes[8], P3 = in_sizes[12];
    int Ptot = P1 + P2 + P3;
    int B = in_sizes[1];
    int rowlen = in_sizes[0] / NX0;   // C*U

    k_sortpaths<<<1, 256>>>(idx1, w1, o1, c1, idx2, w2, o2, c2,
                            idx3, w3, o3, c3, P1, P2, P3);
    k_hist<<<1, 1024>>>(i0, B);
    k_scatter<<<(B + 255) / 256, 256>>>(i0, B);
    int gridMain = (B + TBB - 1) / TBB + 16;
    k_binfo<<<1, 1024>>>(gridMain);
    int tot = NX0 * Ptot * U;
    k_g0c<<<(tot + 255) / 256, 256>>>(x0, Ptot, rowlen);

    size_t smem = (size_t)Ptot * U * 4 + (size_t)S_SEG * U * NL * 4
                + (size_t)Ptot * 4 + NSEG * 3 * 4 + (NTEAM + 1) * 4;
    cudaFuncSetAttribute(k_main, cudaFuncAttributeMaxDynamicSharedMemorySize,
                         (int)smem);
    k_main<<<gridMain, 512, smem>>>(x1, (float*)d_out, B, Ptot);
}

// round 3
// speedup vs baseline: 2.6255x; 1.2147x over previous
#include <cuda_runtime.h>
#include <cuda_pipeline.h>

// ---------------------------------------------------------------------------
// Symmetric contraction (MACE-style) for GB300 — R3.
//   out[b, o_p*U + u] += c_p * x0[i0[b], w_p*U + u] * prod_k x1[b, idx_{p,k}*U + u]
//
// R3 changes vs R2:
//   * x1 staged ROW-MAJOR via cp.async, double-buffered: DRAM latency of the
//     per-group 64KB x1 fetch is hidden under compute (R2 serialized it).
//   * setup fused into 3 launches (sortpaths+hist / scatter / binfo+g0c).
// ---------------------------------------------------------------------------

#define U       128
#define NSEG    16
#define S_SEG   32
#define SU      (S_SEG * U)      // 4096 floats per x1 row
#define NX0     10
#define TBB     32               // batch rows per block
#define NL      4                // concurrent batch rows
#define NTEAM   4                // segment-split teams (512 threads)
#define PCAP    256
#define BSORT_CAP 32768
#define BINFO_CAP 8192

struct BInfo { int bin; int start; int count; };

__device__ int   d_binstart[24];
__device__ int   d_cursor[20];
__device__ int   d_bsort[BSORT_CAP];
__device__ BInfo d_binfo[BINFO_CAP];
__device__ int   d_meta[PCAP];
__device__ int   d_ends[NSEG * 3];
__device__ int   d_tseg[NTEAM + 1];
__device__ int   d_spw[PCAP];
__device__ float d_spc[PCAP];
__device__ float d_g0c[NX0 * PCAP * U];   // [row][sorted_path][u]

// ---------------- setup A: path counting-sort + i0 histogram ----------------
__global__ void k_setupA(const int* __restrict__ idx1, const int* __restrict__ w1,
                         const int* __restrict__ o1, const float* __restrict__ c1,
                         const int* __restrict__ idx2, const int* __restrict__ w2,
                         const int* __restrict__ o2, const float* __restrict__ c2,
                         const int* __restrict__ idx3, const int* __restrict__ w3,
                         const int* __restrict__ o3, const float* __restrict__ c3,
                         int P1, int P2, int P3,
                         const int* __restrict__ i0, int B) {
    __shared__ int cnt[NSEG * 3];
    __shared__ int cur[NSEG * 3];
    __shared__ int h[16];
    int t = threadIdx.x;
    int Ptot = P1 + P2 + P3;
    if (t < NSEG * 3) cnt[t] = 0;
    if (t < 16) h[t] = 0;
    __syncthreads();

    // ---- path key histogram + i0 histogram (same pass) ----
    for (int p = t; p < Ptot; p += blockDim.x) {
        int key;
        if (p < P1)            key = o1[p] * 3 + 0;
        else if (p < P1 + P2)  key = o2[p - P1] * 3 + 1;
        else                   key = o3[p - P1 - P2] * 3 + 2;
        atomicAdd(&cnt[key], 1);
    }
    for (int b = t; b < B; b += blockDim.x) atomicAdd(&h[i0[b] & 15], 1);
    __syncthreads();

    if (t == 0) {
        int run = 0;
        for (int k = 0; k < NSEG * 3; ++k) {
            cur[k] = run; run += cnt[k]; d_ends[k] = run;
        }
        // cost-balanced contiguous segment partition (weights 5/9/13)
        float segc[NSEG]; float tot = 0.f;
        for (int s = 0; s < NSEG; ++s) {
            segc[s] = 5.f * cnt[s*3] + 9.f * cnt[s*3+1] + 13.f * cnt[s*3+2];
            tot += segc[s];
        }
        d_tseg[0] = 0; d_tseg[NTEAM] = NSEG;
        float acc = 0.f; int team = 1;
        for (int s = 0; s < NSEG && team < NTEAM; ++s) {
            acc += segc[s];
            if (acc >= tot * team / NTEAM) { d_tseg[team] = s + 1; ++team; }
        }
        for (; team < NTEAM; ++team) d_tseg[team] = NSEG;
    }
    if (t == 1 || (blockDim.x == 1 && t == 0)) {
        int run = 0;
        for (int bin = 0; bin < 16; ++bin) {
            d_binstart[bin] = run; d_cursor[bin] = run; run += h[bin];
        }
        d_binstart[16] = run;
    }
    __syncthreads();

    // ---- scatter paths into sorted order ----
    for (int p = t; p < Ptot; p += blockDim.x) {
        int key, meta, w; float c;
        if (p < P1) {
            key = o1[p] * 3 + 0; meta = idx1[p]; w = w1[p]; c = c1[p];
        } else if (p < P1 + P2) {
            int q = p - P1;
            key = o2[q] * 3 + 1;
            meta = idx2[q*2] | (idx2[q*2+1] << 8);
            w = w2[q]; c = c2[q];
        } else {
            int q = p - P1 - P2;
            key = o3[q] * 3 + 2;
            meta = idx3[q*3] | (idx3[q*3+1] << 8) | (idx3[q*3+2] << 16);
            w = w3[q]; c = c3[q];
        }
        int pos = atomicAdd(&cur[key], 1);
        d_meta[pos] = meta; d_spw[pos] = w; d_spc[pos] = c;
    }
}

// ---------------- scatter batch indices into bin-sorted order ---------------
__global__ void k_scatter(const int* __restrict__ i0, int B) {
    int b = blockIdx.x * blockDim.x + threadIdx.x;
    if (b < B) {
        int pos = atomicAdd(&d_cursor[i0[b] & 15], 1);
        if (pos < BSORT_CAP) d_bsort[pos] = b;
    }
}

// ---------------- setup B: block0 = binfo, rest = g0c table -----------------
__global__ void k_setupB(const float* __restrict__ x0, int Ptot, int rowlen,
                         int gridMain) {
    if (blockIdx.x == 0) {
        __shared__ int pref[17];
        int t = threadIdx.x;
        if (t == 0) {
            int run = 0;
            for (int bin = 0; bin < 16; ++bin) {
                pref[bin] = run;
                int c = d_binstart[bin + 1] - d_binstart[bin];
                run += (c + TBB - 1) / TBB;
            }
            pref[16] = run;
        }
        __syncthreads();
        int nb = pref[16];
        for (int i = t; i < gridMain && i < BINFO_CAP; i += blockDim.x) {
            if (i >= nb) { d_binfo[i].count = 0; continue; }
            int bin = 0;
            while (pref[bin + 1] <= i) ++bin;
            int start = d_binstart[bin] + (i - pref[bin]) * TBB;
            d_binfo[i].bin = bin;
            d_binfo[i].start = start;
            d_binfo[i].count = min(TBB, d_binstart[bin + 1] - start);
        }
    } else {
        int i = (blockIdx.x - 1) * blockDim.x + threadIdx.x;
        int tot = NX0 * Ptot * U;
        if (i >= tot) return;
        int u  = i & (U - 1);
        int sp = (i >> 7) % Ptot;
        int r  = i / (Ptot * U);
        d_g0c[r * (PCAP * U) + sp * U + u] =
            x0[(size_t)r * rowlen + d_spw[sp] * U + u] * d_spc[sp];
    }
}

// ---------------- main contraction kernel -----------------------------------
__global__ __launch_bounds__(512, 1)
void k_main(const float* __restrict__ x1, float* __restrict__ out,
            int B, int Ptot) {
    extern __shared__ float sm[];
    float* g0s = sm;                              // [Ptot][U]
    float* x1s = sm + Ptot * U;                   // 2 buffers x [NL][SU]
    int* metas = (int*)(x1s + 2 * NL * SU);       // [Ptot]
    int* endss = metas + Ptot;                    // [NSEG*3]
    int* tsegs = endss + NSEG * 3;                // [NTEAM+1]

    BInfo bi = d_binfo[blockIdx.x];
    if (bi.count <= 0) return;
    const int tid  = threadIdx.x;
    const int u    = tid & (U - 1);
    const int team = tid >> 7;

    const int ngroups = (bi.count + NL - 1) / NL;

    // ---- prefetch helper: group g -> buffer (g&1), 16B chunks via cp.async
    auto prefetch = [&](int g) {
        float* dst = x1s + (g & 1) * (NL * SU);
        int base = bi.start + g * NL;
        int b0 = d_bsort[min(base + 0, B - 1)];
        int b1 = d_bsort[min(base + 1, B - 1)];
        int b2 = d_bsort[min(base + 2, B - 1)];
        int b3 = d_bsort[min(base + 3, B - 1)];
        const float* srcs[NL] = {
            x1 + (size_t)b0 * SU, x1 + (size_t)b1 * SU,
            x1 + (size_t)b2 * SU, x1 + (size_t)b3 * SU };
        // NL*SU/4 = 4096 16B chunks, 8 per thread
        #pragma unroll
        for (int k = 0; k < (NL * SU / 4) / 512; ++k) {
            int j = k * 512 + tid;
            int row = j >> 10;               // SU/4 = 1024 chunks per row
            int off = (j & 1023) * 4;
            __pipeline_memcpy_async(dst + row * SU + off, srcs[row] + off, 16);
        }
    };

    // issue prefetch of group 0, then stage g0 under its shadow
    prefetch(0);
    __pipeline_commit();

    {
        const float4* src = (const float4*)(d_g0c + (size_t)bi.bin * (PCAP * U));
        float4* dst = (float4*)g0s;
        int n4 = (Ptot * U) >> 2;
        for (int i = tid; i < n4; i += 512) dst[i] = __ldg(src + i);
        for (int i = tid; i < Ptot; i += 512) metas[i] = d_meta[i];
        if (tid < NSEG * 3) endss[tid] = d_ends[tid];
        if (tid < NTEAM + 1) tsegs[tid] = d_tseg[tid];
    }
    __syncthreads();

    const int segLo = tsegs[team];
    const int segHi = tsegs[team + 1];

    for (int g = 0; g < ngroups; ++g) {
        // prefetch next group into the other buffer (previous compute on that
        // buffer finished before the trailing __syncthreads of iteration g-1)
        if (g + 1 < ngroups) prefetch(g + 1);
        __pipeline_commit();              // (empty group if no next -> keeps FIFO math)
        __pipeline_wait_prior(1);         // current group's data resident
        __syncthreads();

        int r = g * NL;
        int nb = bi.count - r; if (nb > NL) nb = NL;
        int b0 = d_bsort[bi.start + r];
        int b1 = d_bsort[min(bi.start + r + 1, B - 1)];
        int b2 = d_bsort[min(bi.start + r + 2, B - 1)];
        int b3 = d_bsort[min(bi.start + r + 3, B - 1)];

        const float* xb = x1s + (g & 1) * (NL * SU);
        #pragma unroll 1
        for (int seg = segLo; seg < segHi; ++seg) {
            float a0 = 0.f, a1 = 0.f, a2 = 0.f, a3 = 0.f;
            int p  = seg ? endss[seg * 3 - 1] : 0;
            int e1 = endss[seg * 3 + 0];
            int e2 = endss[seg * 3 + 1];
            int e3 = endss[seg * 3 + 2];
            // degree-1
            for (; p < e1; ++p) {
                float gv = g0s[p * U + u];
                int m = metas[p];
                int oa = (m & 255) * U + u;
                a0 = fmaf(gv, xb[oa           ], a0);
                a1 = fmaf(gv, xb[oa +     SU  ], a1);
                a2 = fmaf(gv, xb[oa + 2 * SU  ], a2);
                a3 = fmaf(gv, xb[oa + 3 * SU  ], a3);
            }
            // degree-2
            for (; p < e2; ++p) {
                float gv = g0s[p * U + u];
                int m = metas[p];
                int oa = (m & 255) * U + u;
                int ob = ((m >> 8) & 255) * U + u;
                a0 = fmaf(gv, xb[oa          ] * xb[ob          ], a0);
                a1 = fmaf(gv, xb[oa +     SU ] * xb[ob +     SU ], a1);
                a2 = fmaf(gv, xb[oa + 2 * SU ] * xb[ob + 2 * SU ], a2);
                a3 = fmaf(gv, xb[oa + 3 * SU ] * xb[ob + 3 * SU ], a3);
            }
            // degree-3
            for (; p < e3; ++p) {
                float gv = g0s[p * U + u];
                int m = metas[p];
                int oa = (m & 255) * U + u;
                int ob = ((m >> 8) & 255) * U + u;
                int oc = ((m >> 16) & 255) * U + u;
                a0 = fmaf(gv, xb[oa          ] * xb[ob          ] * xb[oc          ], a0);
                a1 = fmaf(gv, xb[oa +     SU ] * xb[ob +     SU ] * xb[oc +     SU ], a1);
                a2 = fmaf(gv, xb[oa + 2 * SU ] * xb[ob + 2 * SU ] * xb[oc + 2 * SU ], a2);
                a3 = fmaf(gv, xb[oa + 3 * SU ] * xb[ob + 3 * SU ] * xb[oc + 3 * SU ], a3);
            }
            size_t so = (size_t)seg * U + u;
            out[(size_t)b0 * (NSEG * U) + so] = a0;
            if (nb > 1) out[(size_t)b1 * (NSEG * U) + so] = a1;
            if (nb > 2) out[(size_t)b2 * (NSEG * U) + so] = a2;
            if (nb > 3) out[(size_t)b3 * (NSEG * U) + so] = a3;
        }
        __syncthreads();   // all teams done reading xb before buffer reuse
    }
}

// ---------------- launch -----------------------------------------------------
extern "C" void kernel_launch(void* const* d_in, const int* in_sizes, int n_in,
                              void* d_out, int out_size) {
    const float* x0   = (const float*)d_in[0];
    const int*   i0   = (const int*)  d_in[1];
    const float* x1   = (const float*)d_in[2];
    const int*   idx1 = (const int*)  d_in[3];
    const int*   w1   = (const int*)  d_in[4];
    const int*   o1   = (const int*)  d_in[5];
    const float* c1   = (const float*)d_in[6];
    const int*   idx2 = (const int*)  d_in[7];
    const int*   w2   = (const int*)  d_in[8];
    const int*   o2   = (const int*)  d_in[9];
    const float* c2   = (const float*)d_in[10];
    const int*   idx3 = (const int*)  d_in[11];
    const int*   w3   = (const int*)  d_in[12];
    const int*   o3   = (const int*)  d_in[13];
    const float* c3   = (const float*)d_in[14];

    int P1 = in_sizes[4], P2 = in_sizes[8], P3 = in_sizes[12];
    int Ptot = P1 + P2 + P3;
    int B = in_sizes[1];
    int rowlen = in_sizes[0] / NX0;   // C*U

    k_setupA<<<1, 1024>>>(idx1, w1, o1, c1, idx2, w2, o2, c2,
                          idx3, w3, o3, c3, P1, P2, P3, i0, B);
    k_scatter<<<(B + 255) / 256, 256>>>(i0, B);

    int gridMain = (B + TBB - 1) / TBB + 16;
    int tot = NX0 * Ptot * U;
    int gB = 1 + (tot + 255) / 256;
    k_setupB<<<gB, 256>>>(x0, Ptot, rowlen, gridMain);

    size_t smem = (size_t)Ptot * U * 4            // g0s
                + (size_t)2 * NL * SU * 4         // x1 double buffer
                + (size_t)Ptot * 4 + NSEG * 3 * 4 + (NTEAM + 1) * 4;
    cudaFuncSetAttribute(k_main, cudaFuncAttributeMaxDynamicSharedMemorySize,
                         (int)smem);
    k_main<<<gridMain, 512, smem>>>(x1, (float*)d_out, B, Ptot);
}